// round 4
// baseline (speedup 1.0000x reference)
#include <cuda_runtime.h>
#include <cstdint>

#define N_NODES 50000
#define NE      800000
#define HD      64
#define TSTEPS  4
#define STRIDE  68   // 64 + 4 pad floats: 272B rows (16B-aligned), bank spread

// ---------- device scratch ----------
__device__ float g_deg[N_NODES];
__device__ float g_sw[N_NODES];
__device__ float g_c3[TSTEPS * HD];
__device__ float g_S[HD];

// ---------- f32x2 helpers ----------
__device__ __forceinline__ void ffma2(uint64_t& acc, uint64_t a, uint64_t b) {
    asm("fma.rn.f32x2 %0, %1, %2, %0;" : "+l"(acc) : "l"(a), "l"(b));
}
__device__ __forceinline__ uint64_t splat2(float v) {
    uint64_t r;
    asm("mov.b64 %0, {%1, %1};" : "=l"(r) : "f"(v));
    return r;
}
__device__ __forceinline__ float2 unpack2(uint64_t v) {
    float lo, hi;
    asm("mov.b64 {%0, %1}, %2;" : "=f"(lo), "=f"(hi) : "l"(v));
    return make_float2(lo, hi);
}
__device__ __forceinline__ uint32_t sptr(const void* p) {
    uint32_t r;
    asm("{.reg .u64 t; cvta.to.shared.u64 t, %1; cvt.u32.u64 %0, t;}"
        : "=r"(r) : "l"(p));
    return r;
}
__device__ __forceinline__ void lds_v2u64(uint64_t& a, uint64_t& b, uint32_t off) {
    asm("ld.shared.v2.u64 {%0, %1}, [%2];" : "=l"(a), "=l"(b) : "r"(off));
}

// ---------- tiny kernels ----------
__global__ void init_kernel() {
    int i = blockIdx.x * blockDim.x + threadIdx.x;
    if (i < N_NODES) { g_deg[i] = 0.f; g_sw[i] = 0.f; }
    if (i < HD) g_S[i] = 0.f;
}

// edge_index is int32 (JAX x64 disabled); row 1 at offset NE
__global__ void edge_kernel(const int* __restrict__ ei,
                            const float* __restrict__ ew) {
    int e = blockIdx.x * blockDim.x + threadIdx.x;
    if (e < NE) {
        int v = ei[NE + e];
        if (v >= 0 && v < N_NODES) {
            atomicAdd(&g_deg[v], 1.0f);
            atomicAdd(&g_sw[v], ew[e]);
        }
    }
}

// c3[t][h] = sum_k W3[t,h,k] * relu(W4[t,k])
__global__ void c3_kernel(const float* __restrict__ W3,
                          const float* __restrict__ W4) {
    __shared__ float rw4[HD];
    int t = blockIdx.x;
    int h = threadIdx.x;
    rw4[h] = fmaxf(W4[t * HD + h], 0.f);
    __syncthreads();
    float s = 0.f;
    const float* row = W3 + t * HD * HD + h * HD;
#pragma unroll 16
    for (int k = 0; k < HD; k++) s = fmaf(row[k], rw4[k], s);
    g_c3[t * HD + h] = s;
}

// ---------- fused kernel: 4 S2V steps + readout; 64-node tile, 128 threads ----------
// Thread tile: 4 rows x 8 cols. Column pairs packed in u64 for FFMA2.
__global__ void __launch_bounds__(128)
fused_kernel(const float* __restrict__ mu, const float* __restrict__ x,
             const float* __restrict__ W1, const float* __restrict__ W2,
             const float* __restrict__ W5, const float* __restrict__ W7,
             float* __restrict__ out) {
    __shared__ __align__(16) float Ws[HD][STRIDE];    // Ws[k][h] = W[h][k]
    __shared__ __align__(16) float muT[HD][STRIDE];   // muT[k][row]
    __shared__ float xs[64], degs[64], sws[64];
    __shared__ float w1s[64], c3s[64];
    __shared__ float red[64][9];
    __shared__ float colp[2][64];

    const int tid = threadIdx.x;
    const int tx = tid & 7;      // col group: cols tx*8 .. tx*8+7
    const int ty = tid >> 3;     // row group: rows ty*4 .. ty*4+3
    const int c0 = tx * 8;
    const int r0 = ty * 4;
    const int v0 = blockIdx.x * 64;

    const uint32_t ws_base  = sptr(&Ws[0][c0]);
    const uint32_t row_step = STRIDE * 4;

    // load mu tile (coalesced reads, transposed smem writes)
    for (int i = tid; i < 64 * 64; i += 128) {
        int r = i >> 6, k = i & 63;
        int v = v0 + r;
        muT[k][r] = (v < N_NODES) ? mu[v * 64 + k] : 0.f;
    }
    if (tid < 64) {
        int v = v0 + tid;
        xs[tid]   = (v < N_NODES) ? x[v]     : 0.f;
        degs[tid] = (v < N_NODES) ? g_deg[v] : 0.f;
        sws[tid]  = (v < N_NODES) ? g_sw[v]  : 0.f;
    }

#pragma unroll 1
    for (int t = 0; t < TSTEPS; t++) {
        __syncthreads();
        for (int i = tid; i < 64 * 64; i += 128)
            Ws[i & 63][i >> 6] = W2[t * 4096 + i];
        if (tid < 64) { w1s[tid] = W1[t * 64 + tid]; c3s[tid] = g_c3[t * 64 + tid]; }
        __syncthreads();

        uint64_t acc[4][4];     // [col-pair][row]
#pragma unroll
        for (int i = 0; i < 4; i++)
#pragma unroll
            for (int j = 0; j < 4; j++) acc[i][j] = 0ULL;

        uint32_t woff = ws_base;
#pragma unroll 8
        for (int k = 0; k < 64; k++) {
            uint64_t w01, w23, w45, w67;
            lds_v2u64(w01, w23, woff);
            lds_v2u64(w45, w67, woff + 16);
            woff += row_step;
            float4 m = *(const float4*)&muT[k][r0];
            uint64_t m0 = splat2(m.x), m1 = splat2(m.y),
                     m2 = splat2(m.z), m3 = splat2(m.w);
            ffma2(acc[0][0], w01, m0); ffma2(acc[0][1], w01, m1);
            ffma2(acc[0][2], w01, m2); ffma2(acc[0][3], w01, m3);
            ffma2(acc[1][0], w23, m0); ffma2(acc[1][1], w23, m1);
            ffma2(acc[1][2], w23, m2); ffma2(acc[1][3], w23, m3);
            ffma2(acc[2][0], w45, m0); ffma2(acc[2][1], w45, m1);
            ffma2(acc[2][2], w45, m2); ffma2(acc[2][3], w45, m3);
            ffma2(acc[3][0], w67, m0); ffma2(acc[3][1], w67, m1);
            ffma2(acc[3][2], w67, m2); ffma2(acc[3][3], w67, m3);
        }
        __syncthreads();   // all muT reads done before overwrite

        // epilogue: mu' = relu(x*w1 + deg*(mu@W2^T) + sw*c3), write transposed
#pragma unroll
        for (int i = 0; i < 4; i++) {
            int ca = c0 + 2 * i, cb = ca + 1;
            float w1a = w1s[ca], w1b = w1s[cb];
            float c3a = c3s[ca], c3b = c3s[cb];
#pragma unroll
            for (int j = 0; j < 4; j++) {
                int r = r0 + j;
                float2 p = unpack2(acc[i][j]);
                float xr = xs[r], dr = degs[r], sr = sws[r];
                muT[ca][r] = fmaxf(fmaf(xr, w1a, fmaf(dr, p.x, sr * c3a)), 0.f);
                muT[cb][r] = fmaxf(fmaf(xr, w1b, fmaf(dr, p.y, sr * c3b)), 0.f);
            }
        }
    }
    __syncthreads();

    // graph-pool column partials
    {
        int h = tid & 63, g = tid >> 6;
        float s = 0.f;
#pragma unroll
        for (int j = 0; j < 32; j++) s += muT[h][g * 32 + j];
        colp[g][h] = s;
    }
    // load W7^T and W5 node-half (disjoint smem)
    for (int i = tid; i < 64 * 64; i += 128)
        Ws[i & 63][i >> 6] = W7[i];
    if (tid < 64) w1s[tid] = W5[64 + tid];
    __syncthreads();

    if (tid < 64)
        atomicAdd(&g_S[tid], colp[0][tid] + colp[1][tid]);

    // final GEMM: nodes_vec = mu @ W7^T
    uint64_t acc[4][4];
#pragma unroll
    for (int i = 0; i < 4; i++)
#pragma unroll
        for (int j = 0; j < 4; j++) acc[i][j] = 0ULL;

    uint32_t woff = ws_base;
#pragma unroll 8
    for (int k = 0; k < 64; k++) {
        uint64_t w01, w23, w45, w67;
        lds_v2u64(w01, w23, woff);
        lds_v2u64(w45, w67, woff + 16);
        woff += row_step;
        float4 m = *(const float4*)&muT[k][r0];
        uint64_t m0 = splat2(m.x), m1 = splat2(m.y),
                 m2 = splat2(m.z), m3 = splat2(m.w);
        ffma2(acc[0][0], w01, m0); ffma2(acc[0][1], w01, m1);
        ffma2(acc[0][2], w01, m2); ffma2(acc[0][3], w01, m3);
        ffma2(acc[1][0], w23, m0); ffma2(acc[1][1], w23, m1);
        ffma2(acc[1][2], w23, m2); ffma2(acc[1][3], w23, m3);
        ffma2(acc[2][0], w45, m0); ffma2(acc[2][1], w45, m1);
        ffma2(acc[2][2], w45, m2); ffma2(acc[2][3], w45, m3);
        ffma2(acc[3][0], w67, m0); ffma2(acc[3][1], w67, m1);
        ffma2(acc[3][2], w67, m2); ffma2(acc[3][3], w67, m3);
    }

    // per-row partial of sum_c relu(nv)*W5b[c]
    float pr[4] = {0.f, 0.f, 0.f, 0.f};
#pragma unroll
    for (int i = 0; i < 4; i++) {
        float wa = w1s[c0 + 2 * i], wb = w1s[c0 + 2 * i + 1];
#pragma unroll
        for (int j = 0; j < 4; j++) {
            float2 p = unpack2(acc[i][j]);
            pr[j] = fmaf(fmaxf(p.x, 0.f), wa, fmaf(fmaxf(p.y, 0.f), wb, pr[j]));
        }
    }
    red[r0 + 0][tx] = pr[0];
    red[r0 + 1][tx] = pr[1];
    red[r0 + 2][tx] = pr[2];
    red[r0 + 3][tx] = pr[3];
    __syncthreads();

    if (tid < 64) {
        float s = 0.f;
#pragma unroll
        for (int q = 0; q < 8; q++) s += red[tid][q];
        int v = v0 + tid;
        if (v < N_NODES) out[v] = s;
    }
}

// fused graph-pool scalar + broadcast add
__global__ void add_kernel(const float* __restrict__ W5, float* __restrict__ out) {
    __shared__ float sh[64];
    __shared__ float cval;
    int tid = threadIdx.x;
    if (tid < 64) sh[tid] = fmaxf(g_S[tid], 0.f) * W5[tid];
    __syncthreads();
    if (tid == 0) {
        float s = 0.f;
#pragma unroll
        for (int i = 0; i < 64; i++) s += sh[i];
        cval = s;
    }
    __syncthreads();
    int v = blockIdx.x * blockDim.x + tid;
    if (v < N_NODES) out[v] += cval;
}

// ---------- launch ----------
extern "C" void kernel_launch(void* const* d_in, const int* in_sizes, int n_in,
                              void* d_out, int out_size) {
    const float* mu = (const float*)d_in[0];
    const float* x  = (const float*)d_in[1];
    const int*   ei = (const int*)d_in[2];     // int32 (JAX x64 disabled)
    const float* ew = (const float*)d_in[3];
    const float* W1 = (const float*)d_in[4];
    const float* W2 = (const float*)d_in[5];
    const float* W3 = (const float*)d_in[6];
    const float* W4 = (const float*)d_in[7];
    const float* W5 = (const float*)d_in[8];
    const float* W7 = (const float*)d_in[9];
    float* out = (float*)d_out;

    init_kernel<<<(N_NODES + 255) / 256, 256>>>();
    edge_kernel<<<(NE + 255) / 256, 256>>>(ei, ew);
    c3_kernel<<<TSTEPS, HD>>>(W3, W4);
    fused_kernel<<<(N_NODES + 63) / 64, 128>>>(mu, x, W1, W2, W5, W7, out);
    add_kernel<<<(N_NODES + 255) / 256, 256>>>(W5, out);
}

// round 5
// speedup vs baseline: 1.1581x; 1.1581x over previous
#include <cuda_runtime.h>
#include <cstdint>

#define N_NODES 50000
#define NE      800000
#define HD      64
#define TSTEPS  4
#define STRIDE  68   // 64 + 4 pad floats per row: 272B, 16B-aligned

// ---------- device scratch ----------
__device__ float g_deg[N_NODES];
__device__ float g_sw[N_NODES];
__device__ float g_c3[TSTEPS * HD];
__device__ float g_S[HD];

// ---------- f32x2 helpers ----------
__device__ __forceinline__ void ffma2(uint64_t& acc, uint64_t a, uint64_t b) {
    asm("fma.rn.f32x2 %0, %1, %2, %0;" : "+l"(acc) : "l"(a), "l"(b));
}
__device__ __forceinline__ uint64_t splat2(float v) {
    uint64_t r;
    asm("mov.b64 %0, {%1, %1};" : "=l"(r) : "f"(v));
    return r;
}
__device__ __forceinline__ float2 unpack2(uint64_t v) {
    float lo, hi;
    asm("mov.b64 {%0, %1}, %2;" : "=f"(lo), "=f"(hi) : "l"(v));
    return make_float2(lo, hi);
}
__device__ __forceinline__ uint32_t sptr(const void* p) {
    uint32_t r;
    asm("{.reg .u64 t; cvta.to.shared.u64 t, %1; cvt.u32.u64 %0, t;}"
        : "=r"(r) : "l"(p));
    return r;
}
__device__ __forceinline__ void lds_v2u64(uint64_t& a, uint64_t& b, uint32_t off) {
    asm("ld.shared.v2.u64 {%0, %1}, [%2];" : "=l"(a), "=l"(b) : "r"(off));
}

// ---------- tiny kernels ----------
__global__ void init_kernel() {
    int i = blockIdx.x * blockDim.x + threadIdx.x;
    if (i < N_NODES) { g_deg[i] = 0.f; g_sw[i] = 0.f; }
    if (i < HD) g_S[i] = 0.f;
}

// edge_index is int32 (JAX x64 disabled); row 1 at offset NE
__global__ void edge_kernel(const int* __restrict__ ei,
                            const float* __restrict__ ew) {
    int e = blockIdx.x * blockDim.x + threadIdx.x;
    if (e < NE) {
        int v = ei[NE + e];
        if (v >= 0 && v < N_NODES) {
            atomicAdd(&g_deg[v], 1.0f);
            atomicAdd(&g_sw[v], ew[e]);
        }
    }
}

// c3[t][h] = sum_k W3[t,h,k] * relu(W4[t,k])
__global__ void c3_kernel(const float* __restrict__ W3,
                          const float* __restrict__ W4) {
    __shared__ float rw4[HD];
    int t = blockIdx.x;
    int h = threadIdx.x;
    rw4[h] = fmaxf(W4[t * HD + h], 0.f);
    __syncthreads();
    float s = 0.f;
    const float* row = W3 + t * HD * HD + h * HD;
#pragma unroll 16
    for (int k = 0; k < HD; k++) s = fmaf(row[k], rw4[k], s);
    g_c3[t * HD + h] = s;
}

// ---------- fused kernel: 4 S2V steps + readout ----------
// 64-node tile, 256 threads. Thread tile: 2 rows x 8 cols,
// cols split {tx*4..tx*4+3} U {32+tx*4..32+tx*4+3} -> conflict-free LDS.
__global__ void __launch_bounds__(256)
fused_kernel(const float* __restrict__ mu, const float* __restrict__ x,
             const float* __restrict__ W1, const float* __restrict__ W2,
             const float* __restrict__ W5, const float* __restrict__ W7,
             float* __restrict__ out) {
    __shared__ __align__(16) float Ws[HD][STRIDE];    // Ws[k][h] = W[h][k]
    __shared__ __align__(16) float muT[HD][STRIDE];   // muT[k][row]
    __shared__ float xs[64], degs[64], sws[64];
    __shared__ float w1s[64], c3s[64];
    __shared__ float red[64][9];
    __shared__ float colp[4][64];

    const int tid = threadIdx.x;
    const int tx = tid & 7;      // col chunk id
    const int ty = tid >> 3;     // row group: rows ty*2, ty*2+1  (ty 0..31)
    const int cA = tx * 4;       // low col chunk
    const int cB = 32 + tx * 4;  // high col chunk
    const int r0 = ty * 2;
    const int v0 = blockIdx.x * 64;

    const uint32_t wsA = sptr(&Ws[0][cA]);
    const uint32_t wsB = wsA + 32 * 4;     // +32 floats
    const uint32_t row_step = STRIDE * 4;

    // load mu tile (coalesced reads, transposed smem writes)
    for (int i = tid; i < 64 * 64; i += 256) {
        int r = i >> 6, k = i & 63;
        int v = v0 + r;
        muT[k][r] = (v < N_NODES) ? mu[v * 64 + k] : 0.f;
    }
    if (tid < 64) {
        int v = v0 + tid;
        xs[tid]   = (v < N_NODES) ? x[v]     : 0.f;
        degs[tid] = (v < N_NODES) ? g_deg[v] : 0.f;
        sws[tid]  = (v < N_NODES) ? g_sw[v]  : 0.f;
    }

#pragma unroll 1
    for (int t = 0; t < TSTEPS; t++) {
        __syncthreads();
        for (int i = tid; i < 64 * 64; i += 256)
            Ws[i & 63][i >> 6] = W2[t * 4096 + i];
        if (tid < 64) { w1s[tid] = W1[t * 64 + tid]; c3s[tid] = g_c3[t * 64 + tid]; }
        __syncthreads();

        // acc[row][colpair]: colpairs (cA,cA+1),(cA+2,cA+3),(cB,cB+1),(cB+2,cB+3)
        uint64_t acc[2][4];
#pragma unroll
        for (int j = 0; j < 2; j++)
#pragma unroll
            for (int i = 0; i < 4; i++) acc[j][i] = 0ULL;

        uint32_t offA = wsA, offB = wsB;
#pragma unroll 8
        for (int k = 0; k < 64; k++) {
            uint64_t wa0, wa1, wb0, wb1;
            lds_v2u64(wa0, wa1, offA);
            lds_v2u64(wb0, wb1, offB);
            offA += row_step; offB += row_step;
            float2 m = *(const float2*)&muT[k][r0];
            uint64_t m0 = splat2(m.x), m1 = splat2(m.y);
            ffma2(acc[0][0], wa0, m0); ffma2(acc[0][1], wa1, m0);
            ffma2(acc[0][2], wb0, m0); ffma2(acc[0][3], wb1, m0);
            ffma2(acc[1][0], wa0, m1); ffma2(acc[1][1], wa1, m1);
            ffma2(acc[1][2], wb0, m1); ffma2(acc[1][3], wb1, m1);
        }
        __syncthreads();   // all muT reads done before overwrite

        // epilogue: mu' = relu(x*w1 + deg*(mu@W2^T) + sw*c3), write transposed
#pragma unroll
        for (int j = 0; j < 2; j++) {
            int r = r0 + j;
            float xr = xs[r], dr = degs[r], sr = sws[r];
#pragma unroll
            for (int i = 0; i < 4; i++) {
                int c = (i < 2) ? (cA + 2 * i) : (cB + 2 * (i - 2));
                float2 p = unpack2(acc[j][i]);
                muT[c][r]     = fmaxf(fmaf(xr, w1s[c],     fmaf(dr, p.x, sr * c3s[c])),     0.f);
                muT[c + 1][r] = fmaxf(fmaf(xr, w1s[c + 1], fmaf(dr, p.y, sr * c3s[c + 1])), 0.f);
            }
        }
    }
    __syncthreads();

    // graph-pool column partials
    {
        int h = tid & 63, g = tid >> 6;
        float s = 0.f;
#pragma unroll
        for (int j = 0; j < 16; j++) s += muT[h][g * 16 + j];
        colp[g][h] = s;
    }
    // load W7^T and W5 node-half (disjoint smem)
    for (int i = tid; i < 64 * 64; i += 256)
        Ws[i & 63][i >> 6] = W7[i];
    if (tid < 64) w1s[tid] = W5[64 + tid];
    __syncthreads();

    if (tid < 64)
        atomicAdd(&g_S[tid], colp[0][tid] + colp[1][tid] + colp[2][tid] + colp[3][tid]);

    // final GEMM: nodes_vec = mu @ W7^T
    uint64_t acc[2][4];
#pragma unroll
    for (int j = 0; j < 2; j++)
#pragma unroll
        for (int i = 0; i < 4; i++) acc[j][i] = 0ULL;

    uint32_t offA = wsA, offB = wsB;
#pragma unroll 8
    for (int k = 0; k < 64; k++) {
        uint64_t wa0, wa1, wb0, wb1;
        lds_v2u64(wa0, wa1, offA);
        lds_v2u64(wb0, wb1, offB);
        offA += row_step; offB += row_step;
        float2 m = *(const float2*)&muT[k][r0];
        uint64_t m0 = splat2(m.x), m1 = splat2(m.y);
        ffma2(acc[0][0], wa0, m0); ffma2(acc[0][1], wa1, m0);
        ffma2(acc[0][2], wb0, m0); ffma2(acc[0][3], wb1, m0);
        ffma2(acc[1][0], wa0, m1); ffma2(acc[1][1], wa1, m1);
        ffma2(acc[1][2], wb0, m1); ffma2(acc[1][3], wb1, m1);
    }

    // per-row partial of sum_c relu(nv)*W5b[c]
    float pr[2] = {0.f, 0.f};
#pragma unroll
    for (int j = 0; j < 2; j++) {
#pragma unroll
        for (int i = 0; i < 4; i++) {
            int c = (i < 2) ? (cA + 2 * i) : (cB + 2 * (i - 2));
            float2 p = unpack2(acc[j][i]);
            pr[j] = fmaf(fmaxf(p.x, 0.f), w1s[c],
                    fmaf(fmaxf(p.y, 0.f), w1s[c + 1], pr[j]));
        }
    }
    red[r0 + 0][tx] = pr[0];
    red[r0 + 1][tx] = pr[1];
    __syncthreads();

    if (tid < 64) {
        float s = 0.f;
#pragma unroll
        for (int q = 0; q < 8; q++) s += red[tid][q];
        int v = v0 + tid;
        if (v < N_NODES) out[v] = s;
    }
}

// fused graph-pool scalar + broadcast add
__global__ void add_kernel(const float* __restrict__ W5, float* __restrict__ out) {
    __shared__ float sh[64];
    __shared__ float cval;
    int tid = threadIdx.x;
    if (tid < 64) sh[tid] = fmaxf(g_S[tid], 0.f) * W5[tid];
    __syncthreads();
    if (tid == 0) {
        float s = 0.f;
#pragma unroll
        for (int i = 0; i < 64; i++) s += sh[i];
        cval = s;
    }
    __syncthreads();
    int v = blockIdx.x * blockDim.x + tid;
    if (v < N_NODES) out[v] += cval;
}

// ---------- launch ----------
extern "C" void kernel_launch(void* const* d_in, const int* in_sizes, int n_in,
                              void* d_out, int out_size) {
    const float* mu = (const float*)d_in[0];
    const float* x  = (const float*)d_in[1];
    const int*   ei = (const int*)d_in[2];     // int32 (JAX x64 disabled)
    const float* ew = (const float*)d_in[3];
    const float* W1 = (const float*)d_in[4];
    const float* W2 = (const float*)d_in[5];
    const float* W3 = (const float*)d_in[6];
    const float* W4 = (const float*)d_in[7];
    const float* W5 = (const float*)d_in[8];
    const float* W7 = (const float*)d_in[9];
    float* out = (float*)d_out;

    init_kernel<<<(N_NODES + 255) / 256, 256>>>();
    edge_kernel<<<(NE + 255) / 256, 256>>>(ei, ew);
    c3_kernel<<<TSTEPS, HD>>>(W3, W4);
    fused_kernel<<<(N_NODES + 63) / 64, 256>>>(mu, x, W1, W2, W5, W7, out);
    add_kernel<<<(N_NODES + 255) / 256, 256>>>(W5, out);
}

// round 6
// speedup vs baseline: 1.6056x; 1.3864x over previous
#include <cuda_runtime.h>
#include <cstdint>

#define N_NODES 50000
#define NPAD    50048   // 64*782
#define NE      800000
#define HD      64
#define TSTEPS  4
#define STRIDE  68      // floats per muT/Ws row: 272B, 16B-aligned, slot-coprime

// ---------- device scratch ----------
__device__ float g_deg[N_NODES];
__device__ float g_sw[N_NODES];
__device__ float g_c3[TSTEPS * HD];
__device__ float g_S[HD];
__device__ float g_WT[5][HD][HD];          // [0..3]=W2[t]^T, [4]=W7^T  (WT[k][h]=W[h][k])
__device__ float g_muT[HD][NPAD];          // transposed mu

// ---------- f32x2 helpers ----------
__device__ __forceinline__ void ffma2(uint64_t& acc, uint64_t a, uint64_t b) {
    asm("fma.rn.f32x2 %0, %1, %2, %0;" : "+l"(acc) : "l"(a), "l"(b));
}
__device__ __forceinline__ uint64_t pack2(float lo, float hi) {
    uint64_t r;
    asm("mov.b64 %0, {%1, %2};" : "=l"(r) : "f"(lo), "f"(hi));
    return r;
}
__device__ __forceinline__ uint64_t splat2(float v) {
    uint64_t r;
    asm("mov.b64 %0, {%1, %1};" : "=l"(r) : "f"(v));
    return r;
}
__device__ __forceinline__ float2 unpack2(uint64_t v) {
    float lo, hi;
    asm("mov.b64 {%0, %1}, %2;" : "=f"(lo), "=f"(hi) : "l"(v));
    return make_float2(lo, hi);
}

// ---------- tiny kernels ----------
__global__ void init_kernel() {
    int i = blockIdx.x * blockDim.x + threadIdx.x;
    if (i < N_NODES) { g_deg[i] = 0.f; g_sw[i] = 0.f; }
    if (i < HD) g_S[i] = 0.f;
}

// edge_index is int32 (JAX x64 disabled); row 1 at offset NE
__global__ void edge_kernel(const int* __restrict__ ei,
                            const float* __restrict__ ew) {
    int e = blockIdx.x * blockDim.x + threadIdx.x;
    if (e < NE) {
        int v = ei[NE + e];
        if (v >= 0 && v < N_NODES) {
            atomicAdd(&g_deg[v], 1.0f);
            atomicAdd(&g_sw[v], ew[e]);
        }
    }
}

// c3[t][h] = sum_k W3[t,h,k] * relu(W4[t,k])
__global__ void c3_kernel(const float* __restrict__ W3,
                          const float* __restrict__ W4) {
    __shared__ float rw4[HD];
    int t = blockIdx.x;
    int h = threadIdx.x;
    rw4[h] = fmaxf(W4[t * HD + h], 0.f);
    __syncthreads();
    float s = 0.f;
    const float* row = W3 + t * HD * HD + h * HD;
#pragma unroll 16
    for (int k = 0; k < HD; k++) s = fmaf(row[k], rw4[k], s);
    g_c3[t * HD + h] = s;
}

// transpose W2 (4 layers) + W7 into g_WT
__global__ void transW_kernel(const float* __restrict__ W2,
                              const float* __restrict__ W7) {
    __shared__ float S[64][65];
    int l = blockIdx.x;
    const float* src = (l < 4) ? (W2 + l * 4096) : W7;
#pragma unroll
    for (int s = 0; s < 16; s++) {
        int j = threadIdx.x + 256 * s;
        S[j >> 6][j & 63] = src[j];
    }
    __syncthreads();
#pragma unroll
    for (int s = 0; s < 16; s++) {
        int j = threadIdx.x + 256 * s;
        g_WT[l][j >> 6][j & 63] = S[j & 63][j >> 6];
    }
}

// transpose mu [N,64] -> g_muT [64,NPAD]
__global__ void transMu_kernel(const float* __restrict__ mu) {
    __shared__ float S[64][65];
    int v0 = blockIdx.x * 64;
#pragma unroll
    for (int s = 0; s < 16; s++) {
        int j = threadIdx.x + 256 * s;
        int r = j >> 6, k = j & 63;
        int v = v0 + r;
        S[r][k] = (v < N_NODES) ? mu[v * 64 + k] : 0.f;
    }
    __syncthreads();
#pragma unroll
    for (int s = 0; s < 16; s++) {
        int j = threadIdx.x + 256 * s;
        int k = j >> 6, r = j & 63;
        g_muT[k][v0 + r] = S[r][k];
    }
}

// ---------- fused kernel: 4 S2V steps + readout ----------
// 64-node tile, 256 threads. Thread tile: rows r0=4*(tid&15), cols c0=4*(tid>>4).
// Per warp: weight loads broadcast (2 addrs), muT loads span all rows (conflict-free),
// epilogue STS.128 conflict-free.
__global__ void __launch_bounds__(256)
fused_kernel(const float* __restrict__ x,
             const float* __restrict__ W1,
             const float* __restrict__ W5,
             float* __restrict__ out) {
    __shared__ __align__(16) float Ws[HD][STRIDE];    // Ws[k][h] = W[h][k]
    __shared__ __align__(16) float muT[HD][STRIDE];   // muT[k][row]
    __shared__ float xs[64], degs[64], sws[64];
    __shared__ float w1s[64], c3s[64];
    __shared__ float red[64][17];
    __shared__ float colp[4][64];

    const int tid = threadIdx.x;
    const int cx = tid >> 4;     // 0..15 col group
    const int qy = tid & 15;     // 0..15 row group
    const int c0 = cx * 4;
    const int r0 = qy * 4;
    const int v0 = blockIdx.x * 64;

    // stage mu tile: straight copy from pre-transposed g_muT (float4 both sides)
#pragma unroll
    for (int s = 0; s < 4; s++) {
        int j = tid + 256 * s;          // 0..1023
        int k = j >> 4, q = j & 15;
        *(float4*)&muT[k][4 * q] = *(const float4*)&g_muT[k][v0 + 4 * q];
    }
    if (tid < 64) {
        int v = v0 + tid;
        xs[tid]   = (v < N_NODES) ? x[v]     : 0.f;
        degs[tid] = (v < N_NODES) ? g_deg[v] : 0.f;
        sws[tid]  = (v < N_NODES) ? g_sw[v]  : 0.f;
    }

#pragma unroll 1
    for (int t = 0; t < TSTEPS; t++) {
        __syncthreads();
        // stage W2[t]^T: straight copy
#pragma unroll
        for (int s = 0; s < 4; s++) {
            int j = tid + 256 * s;
            int k = j >> 4, q = j & 15;
            *(float4*)&Ws[k][4 * q] = *(const float4*)&g_WT[t][k][4 * q];
        }
        if (tid < 64) { w1s[tid] = W1[t * 64 + tid]; c3s[tid] = g_c3[t * 64 + tid]; }
        __syncthreads();

        uint64_t acc[4][2];   // [col i][row pair p]
#pragma unroll
        for (int i = 0; i < 4; i++) { acc[i][0] = 0ULL; acc[i][1] = 0ULL; }

#pragma unroll 8
        for (int k = 0; k < 64; k++) {
            float4 w = *(const float4*)&Ws[k][c0];    // broadcast within warp
            float4 m = *(const float4*)&muT[k][r0];
            uint64_t m01 = pack2(m.x, m.y);
            uint64_t m23 = pack2(m.z, m.w);
            uint64_t wp;
            wp = splat2(w.x); ffma2(acc[0][0], m01, wp); ffma2(acc[0][1], m23, wp);
            wp = splat2(w.y); ffma2(acc[1][0], m01, wp); ffma2(acc[1][1], m23, wp);
            wp = splat2(w.z); ffma2(acc[2][0], m01, wp); ffma2(acc[2][1], m23, wp);
            wp = splat2(w.w); ffma2(acc[3][0], m01, wp); ffma2(acc[3][1], m23, wp);
        }
        __syncthreads();   // all muT reads done before overwrite

        // epilogue: mu' = relu(x*w1 + deg*(mu@W2^T) + sw*c3); conflict-free STS.128
        float x0 = xs[r0], x1 = xs[r0+1], x2 = xs[r0+2], x3 = xs[r0+3];
        float d0 = degs[r0], d1 = degs[r0+1], d2 = degs[r0+2], d3 = degs[r0+3];
        float s0 = sws[r0], s1 = sws[r0+1], s2 = sws[r0+2], s3 = sws[r0+3];
#pragma unroll
        for (int i = 0; i < 4; i++) {
            int c = c0 + i;
            float w1c = w1s[c], c3c = c3s[c];
            float2 pa = unpack2(acc[i][0]);
            float2 pb = unpack2(acc[i][1]);
            float4 o;
            o.x = fmaxf(fmaf(x0, w1c, fmaf(d0, pa.x, s0 * c3c)), 0.f);
            o.y = fmaxf(fmaf(x1, w1c, fmaf(d1, pa.y, s1 * c3c)), 0.f);
            o.z = fmaxf(fmaf(x2, w1c, fmaf(d2, pb.x, s2 * c3c)), 0.f);
            o.w = fmaxf(fmaf(x3, w1c, fmaf(d3, pb.y, s3 * c3c)), 0.f);
            *(float4*)&muT[c][r0] = o;
        }
    }
    __syncthreads();

    // graph-pool column partials
    {
        int h = tid & 63, g = tid >> 6;
        float s = 0.f;
#pragma unroll
        for (int j = 0; j < 16; j++) s += muT[h][g * 16 + j];
        colp[g][h] = s;
    }
    // stage W7^T and W5 node-half (disjoint smem)
#pragma unroll
    for (int s = 0; s < 4; s++) {
        int j = tid + 256 * s;
        int k = j >> 4, q = j & 15;
        *(float4*)&Ws[k][4 * q] = *(const float4*)&g_WT[4][k][4 * q];
    }
    if (tid < 64) w1s[tid] = W5[64 + tid];
    __syncthreads();

    if (tid < 64)
        atomicAdd(&g_S[tid], colp[0][tid] + colp[1][tid] + colp[2][tid] + colp[3][tid]);

    // final GEMM: nodes_vec = mu @ W7^T
    uint64_t acc[4][2];
#pragma unroll
    for (int i = 0; i < 4; i++) { acc[i][0] = 0ULL; acc[i][1] = 0ULL; }

#pragma unroll 8
    for (int k = 0; k < 64; k++) {
        float4 w = *(const float4*)&Ws[k][c0];
        float4 m = *(const float4*)&muT[k][r0];
        uint64_t m01 = pack2(m.x, m.y);
        uint64_t m23 = pack2(m.z, m.w);
        uint64_t wp;
        wp = splat2(w.x); ffma2(acc[0][0], m01, wp); ffma2(acc[0][1], m23, wp);
        wp = splat2(w.y); ffma2(acc[1][0], m01, wp); ffma2(acc[1][1], m23, wp);
        wp = splat2(w.z); ffma2(acc[2][0], m01, wp); ffma2(acc[2][1], m23, wp);
        wp = splat2(w.w); ffma2(acc[3][0], m01, wp); ffma2(acc[3][1], m23, wp);
    }

    // per-row partial of sum_c relu(nv)*W5b[c]
    float pr[4] = {0.f, 0.f, 0.f, 0.f};
#pragma unroll
    for (int i = 0; i < 4; i++) {
        float wb = w1s[c0 + i];
        float2 pa = unpack2(acc[i][0]);
        float2 pb = unpack2(acc[i][1]);
        pr[0] = fmaf(fmaxf(pa.x, 0.f), wb, pr[0]);
        pr[1] = fmaf(fmaxf(pa.y, 0.f), wb, pr[1]);
        pr[2] = fmaf(fmaxf(pb.x, 0.f), wb, pr[2]);
        pr[3] = fmaf(fmaxf(pb.y, 0.f), wb, pr[3]);
    }
    red[r0 + 0][cx] = pr[0];
    red[r0 + 1][cx] = pr[1];
    red[r0 + 2][cx] = pr[2];
    red[r0 + 3][cx] = pr[3];
    __syncthreads();

    if (tid < 64) {
        float s = 0.f;
#pragma unroll
        for (int q = 0; q < 16; q++) s += red[tid][q];
        int v = v0 + tid;
        if (v < N_NODES) out[v] = s;
    }
}

// fused graph-pool scalar + broadcast add
__global__ void add_kernel(const float* __restrict__ W5, float* __restrict__ out) {
    __shared__ float sh[64];
    __shared__ float cval;
    int tid = threadIdx.x;
    if (tid < 64) sh[tid] = fmaxf(g_S[tid], 0.f) * W5[tid];
    __syncthreads();
    if (tid == 0) {
        float s = 0.f;
#pragma unroll
        for (int i = 0; i < 64; i++) s += sh[i];
        cval = s;
    }
    __syncthreads();
    int v = blockIdx.x * blockDim.x + tid;
    if (v < N_NODES) out[v] += cval;
}

// ---------- launch ----------
extern "C" void kernel_launch(void* const* d_in, const int* in_sizes, int n_in,
                              void* d_out, int out_size) {
    const float* mu = (const float*)d_in[0];
    const float* x  = (const float*)d_in[1];
    const int*   ei = (const int*)d_in[2];     // int32 (JAX x64 disabled)
    const float* ew = (const float*)d_in[3];
    const float* W1 = (const float*)d_in[4];
    const float* W2 = (const float*)d_in[5];
    const float* W3 = (const float*)d_in[6];
    const float* W4 = (const float*)d_in[7];
    const float* W5 = (const float*)d_in[8];
    const float* W7 = (const float*)d_in[9];
    float* out = (float*)d_out;

    init_kernel<<<(N_NODES + 255) / 256, 256>>>();
    edge_kernel<<<(NE + 255) / 256, 256>>>(ei, ew);
    c3_kernel<<<TSTEPS, HD>>>(W3, W4);
    transW_kernel<<<5, 256>>>(W2, W7);
    transMu_kernel<<<NPAD / 64, 256>>>(mu);
    fused_kernel<<<NPAD / 64, 256>>>(x, W1, W5, out);
    add_kernel<<<(N_NODES + 255) / 256, 256>>>(W5, out);
}

// round 7
// speedup vs baseline: 1.7336x; 1.0797x over previous
#include <cuda_runtime.h>
#include <cstdint>

#define N_NODES 50000
#define NPAD    50048   // 128*391
#define NE      800000
#define HD      64
#define TSTEPS  4
#define RSTRIDE 132     // muT row stride (floats): 33 16B-slots (odd) -> spread stores
#define WSTRIDE 68      // Ws row stride

// ---------- device scratch ----------
__device__ float g_deg[N_NODES];
__device__ float g_sw[N_NODES];
__device__ float g_c3[TSTEPS * HD];
__device__ float g_S[HD];
__device__ float g_WT[5][HD][HD];      // [0..3]=W2[t]^T, [4]=W7^T
__device__ float g_muT[HD][NPAD];      // transposed mu

// ---------- f32x2 helpers ----------
__device__ __forceinline__ void ffma2(uint64_t& acc, uint64_t a, uint64_t b) {
    asm("fma.rn.f32x2 %0, %1, %2, %0;" : "+l"(acc) : "l"(a), "l"(b));
}
__device__ __forceinline__ uint64_t pack2(float lo, float hi) {
    uint64_t r;
    asm("mov.b64 %0, {%1, %2};" : "=l"(r) : "f"(lo), "f"(hi));
    return r;
}
__device__ __forceinline__ uint64_t splat2(float v) {
    uint64_t r;
    asm("mov.b64 %0, {%1, %1};" : "=l"(r) : "f"(v));
    return r;
}
__device__ __forceinline__ float2 unpack2(uint64_t v) {
    float lo, hi;
    asm("mov.b64 {%0, %1}, %2;" : "=f"(lo), "=f"(hi) : "l"(v));
    return make_float2(lo, hi);
}

// ---------- prep kernel: zero + c3 + transW + transMu, one launch ----------
// blocks [0,782): transMu(64-row tiles)   [coalesced both sides via smem stage]
// blocks [782,978): zero deg/sw
// block  978: c3 (all 4 layers) + zero g_S
// blocks [979,984): transW layer b-979
__global__ void __launch_bounds__(256)
prep_kernel(const float* __restrict__ mu, const float* __restrict__ W2,
            const float* __restrict__ W7, const float* __restrict__ W3,
            const float* __restrict__ W4) {
    __shared__ float S[64][65];
    int b = blockIdx.x;
    int tid = threadIdx.x;

    if (b < 782) {                       // transMu
        int v0 = b * 64;
#pragma unroll
        for (int s = 0; s < 16; s++) {
            int j = tid + 256 * s;
            int r = j >> 6, k = j & 63;
            int v = v0 + r;
            S[r][k] = (v < N_NODES) ? mu[v * 64 + k] : 0.f;
        }
        __syncthreads();
#pragma unroll
        for (int s = 0; s < 16; s++) {
            int j = tid + 256 * s;
            int k = j >> 6, r = j & 63;
            g_muT[k][v0 + r] = S[r][k];
        }
    } else if (b < 978) {                // zero deg/sw
        int i = (b - 782) * 256 + tid;
        if (i < N_NODES) { g_deg[i] = 0.f; g_sw[i] = 0.f; }
    } else if (b == 978) {               // c3 + zero g_S
        int t = tid >> 6, h = tid & 63;
        S[t][h] = fmaxf(W4[t * HD + h], 0.f);    // rw4 in S[0..3][*]
        if (tid < 64) g_S[tid] = 0.f;
        __syncthreads();
        float s = 0.f;
        const float* row = W3 + t * HD * HD + h * HD;
#pragma unroll 16
        for (int k = 0; k < HD; k++) s = fmaf(row[k], S[t][k], s);
        g_c3[t * HD + h] = s;
    } else {                             // transW
        int l = b - 979;
        const float* src = (l < 4) ? (W2 + l * 4096) : W7;
#pragma unroll
        for (int s = 0; s < 16; s++) {
            int j = tid + 256 * s;
            S[j >> 6][j & 63] = src[j];
        }
        __syncthreads();
#pragma unroll
        for (int s = 0; s < 16; s++) {
            int j = tid + 256 * s;
            g_WT[l][j >> 6][j & 63] = S[j & 63][j >> 6];
        }
    }
}

// ---------- edge kernel: 4 edges/thread, vectorized loads ----------
__global__ void edge_kernel(const int* __restrict__ ei,
                            const float* __restrict__ ew) {
    int t4 = blockIdx.x * blockDim.x + threadIdx.x;   // 0 .. NE/4-1
    if (t4 < NE / 4) {
        int4   v4 = *(const int4*)(ei + NE + 4 * t4); // edge_index row 1
        float4 w4 = *(const float4*)(ew + 4 * t4);
        if ((unsigned)v4.x < N_NODES) { atomicAdd(&g_deg[v4.x], 1.0f); atomicAdd(&g_sw[v4.x], w4.x); }
        if ((unsigned)v4.y < N_NODES) { atomicAdd(&g_deg[v4.y], 1.0f); atomicAdd(&g_sw[v4.y], w4.y); }
        if ((unsigned)v4.z < N_NODES) { atomicAdd(&g_deg[v4.z], 1.0f); atomicAdd(&g_sw[v4.z], w4.z); }
        if ((unsigned)v4.w < N_NODES) { atomicAdd(&g_deg[v4.w], 1.0f); atomicAdd(&g_sw[v4.w], w4.w); }
    }
}

// ---------- fused kernel: 4 S2V steps + readout; 128-node tile, 256 threads ----------
// Thread tile: 4 cols (c0=4*(tid>>4)) x 8 rows ({4qy..4qy+3} U {64+4qy..+3}).
__global__ void __launch_bounds__(256)
fused_kernel(const float* __restrict__ x,
             const float* __restrict__ W1,
             const float* __restrict__ W5,
             float* __restrict__ out) {
    __shared__ __align__(16) float Ws[HD][WSTRIDE];
    __shared__ __align__(16) float muT[HD][RSTRIDE];    // [k][row 0..127]
    __shared__ float xs[128], degs[128], sws[128];
    __shared__ float w1s[64], c3s[64];
    __shared__ float colp[4][64];

    float (*red)[17] = (float (*)[17])&muT[0][0];       // alias: used after muT is dead

    const int tid = threadIdx.x;
    const int cx = tid >> 4;       // 0..15
    const int qy = tid & 15;       // 0..15
    const int c0 = cx * 4;
    const int rA = qy * 4;         // rows rA..rA+3
    const int rB = 64 + qy * 4;    // rows rB..rB+3
    const int v0 = blockIdx.x * 128;

    // stage mu tile: 64k x 128rows, straight float4 copies
#pragma unroll
    for (int s = 0; s < 8; s++) {
        int j = tid + 256 * s;             // 0..2047
        int k = j >> 5, q = j & 31;
        *(float4*)&muT[k][4 * q] = *(const float4*)&g_muT[k][v0 + 4 * q];
    }
    if (tid < 128) {
        int v = v0 + tid;
        xs[tid]   = (v < N_NODES) ? x[v]     : 0.f;
        degs[tid] = (v < N_NODES) ? g_deg[v] : 0.f;
        sws[tid]  = (v < N_NODES) ? g_sw[v]  : 0.f;
    }

#pragma unroll 1
    for (int t = 0; t < TSTEPS; t++) {
        __syncthreads();
#pragma unroll
        for (int s = 0; s < 4; s++) {
            int j = tid + 256 * s;
            int k = j >> 4, q = j & 15;
            *(float4*)&Ws[k][4 * q] = *(const float4*)&g_WT[t][k][4 * q];
        }
        if (tid < 64) { w1s[tid] = W1[t * 64 + tid]; c3s[tid] = g_c3[t * 64 + tid]; }
        __syncthreads();

        uint64_t acc[4][4];   // [col i][pair: rA01,rA23,rB01,rB23]
#pragma unroll
        for (int i = 0; i < 4; i++)
#pragma unroll
            for (int p = 0; p < 4; p++) acc[i][p] = 0ULL;

#pragma unroll 8
        for (int k = 0; k < 64; k++) {
            float4 w  = *(const float4*)&Ws[k][c0];     // broadcast (2 addrs/warp)
            float4 mA = *(const float4*)&muT[k][rA];
            float4 mB = *(const float4*)&muT[k][rB];
            uint64_t a01 = pack2(mA.x, mA.y), a23 = pack2(mA.z, mA.w);
            uint64_t b01 = pack2(mB.x, mB.y), b23 = pack2(mB.z, mB.w);
            uint64_t wp;
            wp = splat2(w.x);
            ffma2(acc[0][0], a01, wp); ffma2(acc[0][1], a23, wp);
            ffma2(acc[0][2], b01, wp); ffma2(acc[0][3], b23, wp);
            wp = splat2(w.y);
            ffma2(acc[1][0], a01, wp); ffma2(acc[1][1], a23, wp);
            ffma2(acc[1][2], b01, wp); ffma2(acc[1][3], b23, wp);
            wp = splat2(w.z);
            ffma2(acc[2][0], a01, wp); ffma2(acc[2][1], a23, wp);
            ffma2(acc[2][2], b01, wp); ffma2(acc[2][3], b23, wp);
            wp = splat2(w.w);
            ffma2(acc[3][0], a01, wp); ffma2(acc[3][1], a23, wp);
            ffma2(acc[3][2], b01, wp); ffma2(acc[3][3], b23, wp);
        }
        __syncthreads();   // all muT reads done before overwrite

        // epilogue: mu' = relu(x*w1 + deg*acc + sw*c3), float4 stores
#pragma unroll
        for (int i = 0; i < 4; i++) {
            int c = c0 + i;
            float w1c = w1s[c], c3c = c3s[c];
            float2 p0 = unpack2(acc[i][0]);
            float2 p1 = unpack2(acc[i][1]);
            float4 o;
            o.x = fmaxf(fmaf(xs[rA+0], w1c, fmaf(degs[rA+0], p0.x, sws[rA+0] * c3c)), 0.f);
            o.y = fmaxf(fmaf(xs[rA+1], w1c, fmaf(degs[rA+1], p0.y, sws[rA+1] * c3c)), 0.f);
            o.z = fmaxf(fmaf(xs[rA+2], w1c, fmaf(degs[rA+2], p1.x, sws[rA+2] * c3c)), 0.f);
            o.w = fmaxf(fmaf(xs[rA+3], w1c, fmaf(degs[rA+3], p1.y, sws[rA+3] * c3c)), 0.f);
            *(float4*)&muT[c][rA] = o;
            float2 p2 = unpack2(acc[i][2]);
            float2 p3 = unpack2(acc[i][3]);
            o.x = fmaxf(fmaf(xs[rB+0], w1c, fmaf(degs[rB+0], p2.x, sws[rB+0] * c3c)), 0.f);
            o.y = fmaxf(fmaf(xs[rB+1], w1c, fmaf(degs[rB+1], p2.y, sws[rB+1] * c3c)), 0.f);
            o.z = fmaxf(fmaf(xs[rB+2], w1c, fmaf(degs[rB+2], p3.x, sws[rB+2] * c3c)), 0.f);
            o.w = fmaxf(fmaf(xs[rB+3], w1c, fmaf(degs[rB+3], p3.y, sws[rB+3] * c3c)), 0.f);
            *(float4*)&muT[c][rB] = o;
        }
    }
    __syncthreads();

    // graph-pool column partials over 128 rows
    {
        int h = tid & 63, g = tid >> 6;
        float s = 0.f;
#pragma unroll
        for (int j = 0; j < 32; j++) s += muT[h][g * 32 + j];
        colp[g][h] = s;
    }
    // stage W7^T and W5 node-half
#pragma unroll
    for (int s = 0; s < 4; s++) {
        int j = tid + 256 * s;
        int k = j >> 4, q = j & 15;
        *(float4*)&Ws[k][4 * q] = *(const float4*)&g_WT[4][k][4 * q];
    }
    if (tid < 64) w1s[tid] = W5[64 + tid];
    __syncthreads();

    if (tid < 64)
        atomicAdd(&g_S[tid], colp[0][tid] + colp[1][tid] + colp[2][tid] + colp[3][tid]);

    // final GEMM: nodes_vec = mu @ W7^T
    uint64_t acc[4][4];
#pragma unroll
    for (int i = 0; i < 4; i++)
#pragma unroll
        for (int p = 0; p < 4; p++) acc[i][p] = 0ULL;

#pragma unroll 8
    for (int k = 0; k < 64; k++) {
        float4 w  = *(const float4*)&Ws[k][c0];
        float4 mA = *(const float4*)&muT[k][rA];
        float4 mB = *(const float4*)&muT[k][rB];
        uint64_t a01 = pack2(mA.x, mA.y), a23 = pack2(mA.z, mA.w);
        uint64_t b01 = pack2(mB.x, mB.y), b23 = pack2(mB.z, mB.w);
        uint64_t wp;
        wp = splat2(w.x);
        ffma2(acc[0][0], a01, wp); ffma2(acc[0][1], a23, wp);
        ffma2(acc[0][2], b01, wp); ffma2(acc[0][3], b23, wp);
        wp = splat2(w.y);
        ffma2(acc[1][0], a01, wp); ffma2(acc[1][1], a23, wp);
        ffma2(acc[1][2], b01, wp); ffma2(acc[1][3], b23, wp);
        wp = splat2(w.z);
        ffma2(acc[2][0], a01, wp); ffma2(acc[2][1], a23, wp);
        ffma2(acc[2][2], b01, wp); ffma2(acc[2][3], b23, wp);
        wp = splat2(w.w);
        ffma2(acc[3][0], a01, wp); ffma2(acc[3][1], a23, wp);
        ffma2(acc[3][2], b01, wp); ffma2(acc[3][3], b23, wp);
    }

    // per-row partial of sum_c relu(nv)*W5b[c]
    float prA[4] = {0.f, 0.f, 0.f, 0.f};
    float prB[4] = {0.f, 0.f, 0.f, 0.f};
#pragma unroll
    for (int i = 0; i < 4; i++) {
        float wb = w1s[c0 + i];
        float2 p0 = unpack2(acc[i][0]);
        float2 p1 = unpack2(acc[i][1]);
        float2 p2 = unpack2(acc[i][2]);
        float2 p3 = unpack2(acc[i][3]);
        prA[0] = fmaf(fmaxf(p0.x, 0.f), wb, prA[0]);
        prA[1] = fmaf(fmaxf(p0.y, 0.f), wb, prA[1]);
        prA[2] = fmaf(fmaxf(p1.x, 0.f), wb, prA[2]);
        prA[3] = fmaf(fmaxf(p1.y, 0.f), wb, prA[3]);
        prB[0] = fmaf(fmaxf(p2.x, 0.f), wb, prB[0]);
        prB[1] = fmaf(fmaxf(p2.y, 0.f), wb, prB[1]);
        prB[2] = fmaf(fmaxf(p3.x, 0.f), wb, prB[2]);
        prB[3] = fmaf(fmaxf(p3.y, 0.f), wb, prB[3]);
    }
    __syncthreads();   // muT dead everywhere -> safe to write red alias
#pragma unroll
    for (int j = 0; j < 4; j++) {
        red[rA + j][cx] = prA[j];
        red[rB + j][cx] = prB[j];
    }
    __syncthreads();

    if (tid < 128) {
        float s = 0.f;
#pragma unroll
        for (int q = 0; q < 16; q++) s += red[tid][q];
        int v = v0 + tid;
        if (v < N_NODES) out[v] = s;
    }
}

// fused graph-pool scalar + broadcast add
__global__ void add_kernel(const float* __restrict__ W5, float* __restrict__ out) {
    __shared__ float sh[64];
    __shared__ float cval;
    int tid = threadIdx.x;
    if (tid < 64) sh[tid] = fmaxf(g_S[tid], 0.f) * W5[tid];
    __syncthreads();
    if (tid == 0) {
        float s = 0.f;
#pragma unroll
        for (int i = 0; i < 64; i++) s += sh[i];
        cval = s;
    }
    __syncthreads();
    int v = blockIdx.x * blockDim.x + tid;
    if (v < N_NODES) out[v] += cval;
}

// ---------- launch ----------
extern "C" void kernel_launch(void* const* d_in, const int* in_sizes, int n_in,
                              void* d_out, int out_size) {
    const float* mu = (const float*)d_in[0];
    const float* x  = (const float*)d_in[1];
    const int*   ei = (const int*)d_in[2];     // int32 (JAX x64 disabled)
    const float* ew = (const float*)d_in[3];
    const float* W1 = (const float*)d_in[4];
    const float* W2 = (const float*)d_in[5];
    const float* W3 = (const float*)d_in[6];
    const float* W4 = (const float*)d_in[7];
    const float* W5 = (const float*)d_in[8];
    const float* W7 = (const float*)d_in[9];
    float* out = (float*)d_out;

    prep_kernel<<<984, 256>>>(mu, W2, W7, W3, W4);
    edge_kernel<<<(NE / 4 + 255) / 256, 256>>>(ei, ew);
    fused_kernel<<<NPAD / 128, 256>>>(x, W1, W5, out);
    add_kernel<<<(N_NODES + 255) / 256, 256>>>(W5, out);
}